// round 12
// baseline (speedup 1.0000x reference)
#include <cuda_runtime.h>
#include <cstdint>

#define F 128
#define F4 (F/4)
#define MAX_ATOMS 20000
#define MAX_PAIRS 320000
#define SCAN_THREADS 1024
#define SCAN_PER ((MAX_ATOMS + SCAN_THREADS - 1) / SCAN_THREADS)   // 20

// GEMM tile config: 32 atoms per tile, 256 threads, 2 atoms x 8 cols / thread
#define GA 32
#define GT 256
#define VS 130        // u64 row stride for V smem (96 rows, c-major)

typedef unsigned long long u64;

// Scratch (allocation-free rule: __device__ globals; zero-init at load;
// g_cnt restored to zero by scan_kernel every run — proven in R7)
__device__ float4     g_V[MAX_ATOMS * 3 * F4];   // V[i][c][:] accumulators
__device__ float      g_Wt[F * F];               // Wt[f][g] = W[g][f]
__device__ int        g_cnt[MAX_ATOMS];          // hist counters (self-zeroing)
__device__ int        g_cnt2[MAX_ATOMS];         // stable copy of counts
__device__ int        g_off[MAX_ATOMS];          // bin offsets
__device__ int        g_pos[MAX_PAIRS];          // within-bin position
__device__ int        g_recJ[MAX_PAIRS];         // binned neighbor index
__device__ ulonglong4 g_recP[MAX_PAIRS];         // packed ((xc,xc),(yc,yc),(zc,zc),(c,c))

__device__ __forceinline__ u64 pack64(float a, float b) {
    u64 r; asm("mov.b64 %0, {%1, %2};" : "=l"(r) : "f"(a), "f"(b)); return r;
}
__device__ __forceinline__ float2 unpack64(u64 v) {
    float2 r; asm("mov.b64 {%0, %1}, %2;" : "=f"(r.x), "=f"(r.y) : "l"(v)); return r;
}
#define FMA2(acc, a, b) asm("fma.rn.f32x2 %0, %1, %2, %0;" : "+l"(acc) : "l"(a), "l"(b))

// ---------------------------------------------------------------------------
// K1: prep = W transpose + histogram + within-bin positions
// ---------------------------------------------------------------------------
__global__ void prep_kernel(const float* __restrict__ Wm,
                            const int* __restrict__ pl, int n_pairs) {
    int idx = blockIdx.x * blockDim.x + threadIdx.x;
    if (idx < F * F) {
        int f = idx >> 7, g = idx & (F - 1);
        g_Wt[idx] = Wm[g * F + f];
    }
    if (idx < n_pairs) g_pos[idx] = atomicAdd(&g_cnt[pl[idx]], 1);
}

// ---------------------------------------------------------------------------
// K2: exclusive scan g_cnt -> g_off; copy counts to g_cnt2; zero g_cnt
// ---------------------------------------------------------------------------
__global__ void scan_kernel(int n_atoms) {
    __shared__ int ssum[SCAN_THREADS];
    int t = threadIdx.x;
    int base = t * SCAN_PER;
    int local[SCAN_PER];
    int s = 0;
#pragma unroll
    for (int k = 0; k < SCAN_PER; k++) {
        int idx = base + k;
        int v = 0;
        if (idx < n_atoms) {
            v = g_cnt[idx];
            g_cnt[idx] = 0;
            g_cnt2[idx] = v;
        }
        local[k] = s;
        s += v;
    }
    ssum[t] = s;
    __syncthreads();
    for (int d = 1; d < SCAN_THREADS; d <<= 1) {
        int x = (t >= d) ? ssum[t - d] : 0;
        __syncthreads();
        ssum[t] += x;
        __syncthreads();
    }
    int excl = (t > 0) ? ssum[t - 1] : 0;
#pragma unroll
    for (int k = 0; k < SCAN_PER; k++) {
        int idx = base + k;
        if (idx < n_atoms) g_off[idx] = excl + local[k];
    }
}

// ---------------------------------------------------------------------------
// K3: scatter pairs into bins; records PRE-SCALED and PRE-PACKED (f32x2 dup)
// ---------------------------------------------------------------------------
__global__ void scatter_kernel(const int* __restrict__ pl,
                               const float* __restrict__ cut,
                               const float* __restrict__ rij,
                               int n_pairs) {
    int p = blockIdx.x * blockDim.x + threadIdx.x;
    if (p >= n_pairs) return;
    int   i = pl[p];
    int   j = pl[n_pairs + p];
    float c = cut[p];
    float r0 = rij[3 * p + 0];
    float r1 = rij[3 * p + 1];
    float r2 = rij[3 * p + 2];
    float s = rsqrtf(r0 * r0 + r1 * r1 + r2 * r2) * c;
    int pos = g_off[i] + g_pos[p];
    float xc = r0 * s, yc = r1 * s, zc = r2 * s;
    ulonglong4 rec;
    rec.x = pack64(xc, xc);
    rec.y = pack64(yc, yc);
    rec.z = pack64(zc, zc);
    rec.w = pack64(c, c);
    g_recJ[pos] = j;
    g_recP[pos] = rec;
}

// ---------------------------------------------------------------------------
// K4: gather. One warp per atom; prepacked records staged in smem (broadcast
// LDS); 8 FMA2 + 1 LDG.128 per pair; 4-wide independent load chains;
// 3 blocks/SM via launch bounds for latency hiding.
// ---------------------------------------------------------------------------
struct Acc2 { u64 r0, r1, x0, x1, y0, y1, z0, z1; };

__device__ __forceinline__ void accP(const ulonglong4& u, const ulonglong2& a, Acc2& s) {
    FMA2(s.r0, u.w, a.x); FMA2(s.r1, u.w, a.y);
    FMA2(s.x0, u.x, a.x); FMA2(s.x1, u.x, a.y);
    FMA2(s.y0, u.y, a.x); FMA2(s.y1, u.y, a.y);
    FMA2(s.z0, u.z, a.x); FMA2(s.z1, u.z, a.y);
}

__global__ __launch_bounds__(256, 3)
void gather_kernel(const ulonglong2* __restrict__ A2,
                   float* __restrict__ out, int n_atoms) {
    __shared__ int        sJ[8][32];
    __shared__ ulonglong4 sP[8][32];

    int warp = threadIdx.x >> 5, lane = threadIdx.x & 31;
    int w = blockIdx.x * 8 + warp;
    if (w >= n_atoms) return;
    int n = g_cnt2[w];
    int base = g_off[w];

    Acc2 s = {};

    for (int c0 = 0; c0 < n; c0 += 32) {
        int m = n - c0; if (m > 32) m = 32;
        if (lane < m) {
            sJ[warp][lane] = g_recJ[base + c0 + lane];
            sP[warp][lane] = g_recP[base + c0 + lane];
        }
        __syncwarp();
        int k = 0;
        for (; k + 4 <= m; k += 4) {
            int j0 = sJ[warp][k + 0];
            int j1 = sJ[warp][k + 1];
            int j2 = sJ[warp][k + 2];
            int j3 = sJ[warp][k + 3];
            ulonglong2 a0 = __ldg(&A2[j0 * F4 + lane]);
            ulonglong2 a1 = __ldg(&A2[j1 * F4 + lane]);
            ulonglong2 a2 = __ldg(&A2[j2 * F4 + lane]);
            ulonglong2 a3 = __ldg(&A2[j3 * F4 + lane]);
            accP(sP[warp][k + 0], a0, s);
            accP(sP[warp][k + 1], a1, s);
            accP(sP[warp][k + 2], a2, s);
            accP(sP[warp][k + 3], a3, s);
        }
        for (; k < m; k++) {
            int j0 = sJ[warp][k];
            ulonglong2 a0 = __ldg(&A2[j0 * F4 + lane]);
            accP(sP[warp][k], a0, s);
        }
        __syncwarp();
    }

    float2 p0, p1;
    p0 = unpack64(s.r0); p1 = unpack64(s.r1);
    *(float4*)(out + w * (2 * F) + F + lane * 4) = make_float4(p0.x, p0.y, p1.x, p1.y);
    p0 = unpack64(s.x0); p1 = unpack64(s.x1);
    g_V[(w * 3 + 0) * F4 + lane] = make_float4(p0.x, p0.y, p1.x, p1.y);
    p0 = unpack64(s.y0); p1 = unpack64(s.y1);
    g_V[(w * 3 + 1) * F4 + lane] = make_float4(p0.x, p0.y, p1.x, p1.y);
    p0 = unpack64(s.z0); p1 = unpack64(s.z1);
    g_V[(w * 3 + 2) * F4 + lane] = make_float4(p0.x, p0.y, p1.x, p1.y);
}

// ---------------------------------------------------------------------------
// K5: fused GEMM + norm. 32 atoms/tile, 256 threads. Thread = (ga = t&15
// handling atoms {ga, ga+16}, cg = t>>4 -> cols cg*8..+7). V smem in c-major
// rows (row = c*32 + atom). 96 rows x 32 float4 = 3072 entries ->
// TWELVE staging iterations at GT=256 (the R11 bug was 6).
// ---------------------------------------------------------------------------
__global__ __launch_bounds__(GT)
void gemm_norm_kernel(const float* __restrict__ bias,
                      float* __restrict__ out, int n_atoms) {
    extern __shared__ char smraw[];
    float* Ws = (float*)smraw;                        // [F][F] floats (64KB)
    u64*   VsU = (u64*)(smraw + F * F * 4);           // [96][VS] dup (v,v)
    const ulonglong2* WsU2 = (const ulonglong2*)Ws;   // 32 ull2 per f-row

    int t = threadIdx.x;
    int ga = t & 15;
    int cg = t >> 4;
    int atom0 = blockIdx.x * GA;

    // stage Wt (L2-resident; ~2% of tile work)
    {
        const float4* src = (const float4*)g_Wt;
        float4* dst = (float4*)Ws;
        for (int k = t; k < F * F / 4; k += GT) dst[k] = src[k];
    }

    // stage V in c-major rows, duplicated (v,v): 3072 float4 entries
#pragma unroll
    for (int r = 0; r < 12; r++) {
        int idx = t + r * GT;                 // 0..3071
        int row = idx >> 5, f4 = idx & 31;    // row = c*32 + a
        int a = row & 31, c = row >> 5;
        int atom = atom0 + a;
        float4 v = (atom < n_atoms) ? __ldg(&g_V[(atom * 3 + c) * F4 + f4])
                                    : make_float4(0.f, 0.f, 0.f, 0.f);
        ulonglong2 q0, q1;
        q0.x = pack64(v.x, v.x);
        q0.y = pack64(v.y, v.y);
        q1.x = pack64(v.z, v.z);
        q1.y = pack64(v.w, v.w);
        *(ulonglong2*)&VsU[row * VS + f4 * 4]     = q0;
        *(ulonglong2*)&VsU[row * VS + f4 * 4 + 2] = q1;
    }
    __syncthreads();

    u64 acc[2][3][4] = {};
#pragma unroll 4
    for (int f = 0; f < F; f += 2) {
        ulonglong2 wa0 = WsU2[f * 32 + cg * 2];
        ulonglong2 wa1 = WsU2[f * 32 + cg * 2 + 1];
        ulonglong2 wb0 = WsU2[(f + 1) * 32 + cg * 2];
        ulonglong2 wb1 = WsU2[(f + 1) * 32 + cg * 2 + 1];
#pragma unroll
        for (int ha = 0; ha < 2; ha++) {
            int ab = ga + ha * 16;
#pragma unroll
            for (int c = 0; c < 3; c++) {
                ulonglong2 v = *(const ulonglong2*)&VsU[(c * 32 + ab) * VS + f];
                FMA2(acc[ha][c][0], v.x, wa0.x);
                FMA2(acc[ha][c][1], v.x, wa0.y);
                FMA2(acc[ha][c][2], v.x, wa1.x);
                FMA2(acc[ha][c][3], v.x, wa1.y);
                FMA2(acc[ha][c][0], v.y, wb0.x);
                FMA2(acc[ha][c][1], v.y, wb0.y);
                FMA2(acc[ha][c][2], v.y, wb1.x);
                FMA2(acc[ha][c][3], v.y, wb1.y);
            }
        }
    }

#pragma unroll
    for (int ha = 0; ha < 2; ha++) {
        int atom = atom0 + ga + ha * 16;
        if (atom >= n_atoms) continue;
        float cnt = (float)g_cnt2[atom];
        float4 bv0 = __ldg((const float4*)&bias[cg * 8]);
        float4 bv1 = __ldg((const float4*)&bias[cg * 8 + 4]);
        float bb[8], ob[8];
        bb[0] = bv0.x * cnt; bb[1] = bv0.y * cnt; bb[2] = bv0.z * cnt; bb[3] = bv0.w * cnt;
        bb[4] = bv1.x * cnt; bb[5] = bv1.y * cnt; bb[6] = bv1.z * cnt; bb[7] = bv1.w * cnt;
#pragma unroll
        for (int q = 0; q < 4; q++) {
            float2 vx = unpack64(acc[ha][0][q]);
            float2 vy = unpack64(acc[ha][1][q]);
            float2 vz = unpack64(acc[ha][2][q]);
            float x0 = vx.x + bb[2 * q],     y0 = vy.x + bb[2 * q],     z0 = vz.x + bb[2 * q];
            float x1 = vx.y + bb[2 * q + 1], y1 = vy.y + bb[2 * q + 1], z1 = vz.y + bb[2 * q + 1];
            ob[2 * q]     = sqrtf(x0 * x0 + y0 * y0 + z0 * z0 + 1e-12f);
            ob[2 * q + 1] = sqrtf(x1 * x1 + y1 * y1 + z1 * z1 + 1e-12f);
        }
        float* o = &out[atom * (2 * F) + cg * 8];
        *(float4*)o       = make_float4(ob[0], ob[1], ob[2], ob[3]);
        *(float4*)(o + 4) = make_float4(ob[4], ob[5], ob[6], ob[7]);
    }
}

// ---------------------------------------------------------------------------
// Launch (5 kernels)
// ---------------------------------------------------------------------------
extern "C" void kernel_launch(void* const* d_in, const int* in_sizes, int n_in,
                              void* d_out, int out_size) {
    const float* A   = (const float*)d_in[0];   // [N, F]
    const int*   pl  = (const int*)  d_in[1];   // [2, P]
    const float* cut = (const float*)d_in[2];   // [P, 1]
    const float* rij = (const float*)d_in[3];   // [P, 3]
    const float* Wm  = (const float*)d_in[4];   // [F, F]
    const float* b   = (const float*)d_in[5];   // [F]
    float* out = (float*)d_out;                 // [N, 2F]

    int n_atoms = in_sizes[0] / F;
    int n_pairs = in_sizes[2];

    int prep_n = (n_pairs > F * F) ? n_pairs : F * F;
    prep_kernel<<<(prep_n + 255) / 256, 256>>>(Wm, pl, n_pairs);

    scan_kernel<<<1, SCAN_THREADS>>>(n_atoms);

    scatter_kernel<<<(n_pairs + 255) / 256, 256>>>(pl, cut, rij, n_pairs);

    gather_kernel<<<(n_atoms + 7) / 8, 256>>>((const ulonglong2*)A, out, n_atoms);

    {
        int smem = F * F * 4 + 96 * VS * 8;   // 64KB + 97.5KB
        cudaFuncSetAttribute(gemm_norm_kernel,
                             cudaFuncAttributeMaxDynamicSharedMemorySize, smem);
        int grid = (n_atoms + GA - 1) / GA;   // 625
        gemm_norm_kernel<<<grid, GT, smem>>>(b, out, n_atoms);
    }
}

// round 13
// speedup vs baseline: 1.1387x; 1.1387x over previous
#include <cuda_runtime.h>
#include <cstdint>

#define F 128
#define F4 (F/4)
#define MAX_ATOMS 20000
#define MAX_PAIRS 320000
#define SCAN_THREADS 1024
#define SCAN_PER ((MAX_ATOMS + SCAN_THREADS - 1) / SCAN_THREADS)   // 20

// GEMM tile config (R4-proven): 16 atoms (48 rows) per tile, 256 threads
#define GA 16
#define GT 256
#define VS_STRIDE 130        // u64 row stride

typedef unsigned long long u64;

// Scratch (allocation-free rule: __device__ globals; zero-init at load;
// g_cnt restored to zero by scan_kernel every run)
__device__ float4     g_V[MAX_ATOMS * 3 * F4];   // V[i][c][:] accumulators
__device__ float      g_Wt[F * F];               // Wt[f][g] = W[g][f]
__device__ int        g_cnt[MAX_ATOMS];          // hist counters (self-zeroing)
__device__ int        g_cnt2[MAX_ATOMS];         // stable copy of counts
__device__ int        g_off[MAX_ATOMS];          // bin offsets
__device__ int        g_pos[MAX_PAIRS];          // within-bin position
__device__ int        g_recJ[MAX_PAIRS];         // binned neighbor index
__device__ ulonglong4 g_recP[MAX_PAIRS];         // packed ((xc,xc),(yc,yc),(zc,zc),(c,c))

__device__ __forceinline__ u64 pack64(float a, float b) {
    u64 r; asm("mov.b64 %0, {%1, %2};" : "=l"(r) : "f"(a), "f"(b)); return r;
}
__device__ __forceinline__ float2 unpack64(u64 v) {
    float2 r; asm("mov.b64 {%0, %1}, %2;" : "=f"(r.x), "=f"(r.y) : "l"(v)); return r;
}
#define FMA2(acc, a, b) asm("fma.rn.f32x2 %0, %1, %2, %0;" : "+l"(acc) : "l"(a), "l"(b))

// ---------------------------------------------------------------------------
// K1: prep = W transpose + histogram + within-bin positions (R12-proven)
// ---------------------------------------------------------------------------
__global__ void prep_kernel(const float* __restrict__ Wm,
                            const int* __restrict__ pl, int n_pairs) {
    int idx = blockIdx.x * blockDim.x + threadIdx.x;
    if (idx < F * F) {
        int f = idx >> 7, g = idx & (F - 1);
        g_Wt[idx] = Wm[g * F + f];
    }
    if (idx < n_pairs) g_pos[idx] = atomicAdd(&g_cnt[pl[idx]], 1);
}

// ---------------------------------------------------------------------------
// K2: exclusive scan g_cnt -> g_off; copy counts to g_cnt2; zero g_cnt
// (R12-proven)
// ---------------------------------------------------------------------------
__global__ void scan_kernel(int n_atoms) {
    __shared__ int ssum[SCAN_THREADS];
    int t = threadIdx.x;
    int base = t * SCAN_PER;
    int local[SCAN_PER];
    int s = 0;
#pragma unroll
    for (int k = 0; k < SCAN_PER; k++) {
        int idx = base + k;
        int v = 0;
        if (idx < n_atoms) {
            v = g_cnt[idx];
            g_cnt[idx] = 0;
            g_cnt2[idx] = v;
        }
        local[k] = s;
        s += v;
    }
    ssum[t] = s;
    __syncthreads();
    for (int d = 1; d < SCAN_THREADS; d <<= 1) {
        int x = (t >= d) ? ssum[t - d] : 0;
        __syncthreads();
        ssum[t] += x;
        __syncthreads();
    }
    int excl = (t > 0) ? ssum[t - 1] : 0;
#pragma unroll
    for (int k = 0; k < SCAN_PER; k++) {
        int idx = base + k;
        if (idx < n_atoms) g_off[idx] = excl + local[k];
    }
}

// ---------------------------------------------------------------------------
// K3: scatter pairs into bins; PRE-SCALED, PRE-PACKED records (R12-proven)
// ---------------------------------------------------------------------------
__global__ void scatter_kernel(const int* __restrict__ pl,
                               const float* __restrict__ cut,
                               const float* __restrict__ rij,
                               int n_pairs) {
    int p = blockIdx.x * blockDim.x + threadIdx.x;
    if (p >= n_pairs) return;
    int   i = pl[p];
    int   j = pl[n_pairs + p];
    float c = cut[p];
    float r0 = rij[3 * p + 0];
    float r1 = rij[3 * p + 1];
    float r2 = rij[3 * p + 2];
    float s = rsqrtf(r0 * r0 + r1 * r1 + r2 * r2) * c;
    int pos = g_off[i] + g_pos[p];
    float xc = r0 * s, yc = r1 * s, zc = r2 * s;
    ulonglong4 rec;
    rec.x = pack64(xc, xc);
    rec.y = pack64(yc, yc);
    rec.z = pack64(zc, zc);
    rec.w = pack64(c, c);
    g_recJ[pos] = j;
    g_recP[pos] = rec;
}

// ---------------------------------------------------------------------------
// K4: gather (R12-proven, 29.5us measured). One warp per atom; prepacked
// records staged in smem; 8 FMA2 + 1 LDG.128 per pair; 3 blocks/SM.
// ---------------------------------------------------------------------------
struct Acc2 { u64 r0, r1, x0, x1, y0, y1, z0, z1; };

__device__ __forceinline__ void accP(const ulonglong4& u, const ulonglong2& a, Acc2& s) {
    FMA2(s.r0, u.w, a.x); FMA2(s.r1, u.w, a.y);
    FMA2(s.x0, u.x, a.x); FMA2(s.x1, u.x, a.y);
    FMA2(s.y0, u.y, a.x); FMA2(s.y1, u.y, a.y);
    FMA2(s.z0, u.z, a.x); FMA2(s.z1, u.z, a.y);
}

__global__ __launch_bounds__(256, 3)
void gather_kernel(const ulonglong2* __restrict__ A2,
                   float* __restrict__ out, int n_atoms) {
    __shared__ int        sJ[8][32];
    __shared__ ulonglong4 sP[8][32];

    int warp = threadIdx.x >> 5, lane = threadIdx.x & 31;
    int w = blockIdx.x * 8 + warp;
    if (w >= n_atoms) return;
    int n = g_cnt2[w];
    int base = g_off[w];

    Acc2 s = {};

    for (int c0 = 0; c0 < n; c0 += 32) {
        int m = n - c0; if (m > 32) m = 32;
        if (lane < m) {
            sJ[warp][lane] = g_recJ[base + c0 + lane];
            sP[warp][lane] = g_recP[base + c0 + lane];
        }
        __syncwarp();
        int k = 0;
        for (; k + 4 <= m; k += 4) {
            int j0 = sJ[warp][k + 0];
            int j1 = sJ[warp][k + 1];
            int j2 = sJ[warp][k + 2];
            int j3 = sJ[warp][k + 3];
            ulonglong2 a0 = __ldg(&A2[j0 * F4 + lane]);
            ulonglong2 a1 = __ldg(&A2[j1 * F4 + lane]);
            ulonglong2 a2 = __ldg(&A2[j2 * F4 + lane]);
            ulonglong2 a3 = __ldg(&A2[j3 * F4 + lane]);
            accP(sP[warp][k + 0], a0, s);
            accP(sP[warp][k + 1], a1, s);
            accP(sP[warp][k + 2], a2, s);
            accP(sP[warp][k + 3], a3, s);
        }
        for (; k < m; k++) {
            int j0 = sJ[warp][k];
            ulonglong2 a0 = __ldg(&A2[j0 * F4 + lane]);
            accP(sP[warp][k], a0, s);
        }
        __syncwarp();
    }

    float2 p0, p1;
    p0 = unpack64(s.r0); p1 = unpack64(s.r1);
    *(float4*)(out + w * (2 * F) + F + lane * 4) = make_float4(p0.x, p0.y, p1.x, p1.y);
    p0 = unpack64(s.x0); p1 = unpack64(s.x1);
    g_V[(w * 3 + 0) * F4 + lane] = make_float4(p0.x, p0.y, p1.x, p1.y);
    p0 = unpack64(s.y0); p1 = unpack64(s.y1);
    g_V[(w * 3 + 1) * F4 + lane] = make_float4(p0.x, p0.y, p1.x, p1.y);
    p0 = unpack64(s.z0); p1 = unpack64(s.z1);
    g_V[(w * 3 + 2) * F4 + lane] = make_float4(p0.x, p0.y, p1.x, p1.y);
}

// ---------------------------------------------------------------------------
// K5: fused GEMM + norm — EXACT R4 version (116.8us run), counts from g_cnt2.
// Persistent 296 blocks; 16 atoms/tile; thread = (atom = t&15, cg = t>>4).
// ---------------------------------------------------------------------------
__global__ void gemm_norm_kernel(const float* __restrict__ bias,
                                 float* __restrict__ out, int n_atoms) {
    extern __shared__ char smraw[];
    float* Ws = (float*)smraw;                        // [F][F] floats
    u64*   VsU = (u64*)(smraw + F * F * 4);           // [48][VS_STRIDE] dup (v,v)

    int t = threadIdx.x;
    int ga = t & 15;            // atom in tile
    int cg = t >> 4;            // col group (0..15) -> cols cg*8..+7
    const ulonglong2* WsU2 = (const ulonglong2*)Ws;   // row stride 32 ull2

    {
        const float4* src = (const float4*)g_Wt;
        float4* dst = (float4*)Ws;
        for (int k = t; k < F * F / 4; k += GT) dst[k] = src[k];
    }
    __syncthreads();

    int nrows3 = n_atoms * 3;
    int tiles = (n_atoms + GA - 1) / GA;
    for (int tile = blockIdx.x; tile < tiles; tile += gridDim.x) {
        int row0 = tile * GA * 3;

        float4 vst[6];
#pragma unroll
        for (int r = 0; r < 6; r++) {
            int idx = t + r * GT;            // 0..1535
            int row = idx >> 5, f4 = idx & 31;
            int grow = row0 + row;
            vst[r] = (grow < nrows3)
                       ? __ldg(&g_V[grow * F4 + f4])
                       : make_float4(0.f, 0.f, 0.f, 0.f);
        }
        __syncthreads();
#pragma unroll
        for (int r = 0; r < 6; r++) {
            int idx = t + r * GT;
            int row = idx >> 5, f4 = idx & 31;
            ulonglong2 q0, q1;
            q0.x = pack64(vst[r].x, vst[r].x);
            q0.y = pack64(vst[r].y, vst[r].y);
            q1.x = pack64(vst[r].z, vst[r].z);
            q1.y = pack64(vst[r].w, vst[r].w);
            *(ulonglong2*)&VsU[row * VS_STRIDE + f4 * 4]     = q0;
            *(ulonglong2*)&VsU[row * VS_STRIDE + f4 * 4 + 2] = q1;
        }
        __syncthreads();

        u64 acc[3][4] = {};
#pragma unroll 4
        for (int f = 0; f < F; f += 2) {
            ulonglong2 wa0 = WsU2[f * 32 + cg * 2];
            ulonglong2 wa1 = WsU2[f * 32 + cg * 2 + 1];
            ulonglong2 wb0 = WsU2[(f + 1) * 32 + cg * 2];
            ulonglong2 wb1 = WsU2[(f + 1) * 32 + cg * 2 + 1];
#pragma unroll
            for (int c = 0; c < 3; c++) {
                ulonglong2 v = *(const ulonglong2*)&VsU[(ga * 3 + c) * VS_STRIDE + f];
                FMA2(acc[c][0], v.x, wa0.x);
                FMA2(acc[c][1], v.x, wa0.y);
                FMA2(acc[c][2], v.x, wa1.x);
                FMA2(acc[c][3], v.x, wa1.y);
                FMA2(acc[c][0], v.y, wb0.x);
                FMA2(acc[c][1], v.y, wb0.y);
                FMA2(acc[c][2], v.y, wb1.x);
                FMA2(acc[c][3], v.y, wb1.y);
            }
        }

        int atom = tile * GA + ga;
        if (atom < n_atoms) {
            float cnt = (float)g_cnt2[atom];
            float4 bv0 = __ldg((const float4*)&bias[cg * 8]);
            float4 bv1 = __ldg((const float4*)&bias[cg * 8 + 4]);
            float ob[8], bb[8];
            bb[0] = bv0.x * cnt; bb[1] = bv0.y * cnt; bb[2] = bv0.z * cnt; bb[3] = bv0.w * cnt;
            bb[4] = bv1.x * cnt; bb[5] = bv1.y * cnt; bb[6] = bv1.z * cnt; bb[7] = bv1.w * cnt;
#pragma unroll
            for (int q = 0; q < 4; q++) {
                float2 vx = unpack64(acc[0][q]);
                float2 vy = unpack64(acc[1][q]);
                float2 vz = unpack64(acc[2][q]);
                float x0 = vx.x + bb[2 * q], y0 = vy.x + bb[2 * q], z0 = vz.x + bb[2 * q];
                float x1 = vx.y + bb[2 * q + 1], y1 = vy.y + bb[2 * q + 1], z1 = vz.y + bb[2 * q + 1];
                ob[2 * q]     = sqrtf(x0 * x0 + y0 * y0 + z0 * z0 + 1e-12f);
                ob[2 * q + 1] = sqrtf(x1 * x1 + y1 * y1 + z1 * z1 + 1e-12f);
            }
            float* o = &out[atom * (2 * F) + cg * 8];
            *(float4*)o       = make_float4(ob[0], ob[1], ob[2], ob[3]);
            *(float4*)(o + 4) = make_float4(ob[4], ob[5], ob[6], ob[7]);
        }
    }
}

// ---------------------------------------------------------------------------
// Launch (5 kernels)
// ---------------------------------------------------------------------------
extern "C" void kernel_launch(void* const* d_in, const int* in_sizes, int n_in,
                              void* d_out, int out_size) {
    const float* A   = (const float*)d_in[0];   // [N, F]
    const int*   pl  = (const int*)  d_in[1];   // [2, P]
    const float* cut = (const float*)d_in[2];   // [P, 1]
    const float* rij = (const float*)d_in[3];   // [P, 3]
    const float* Wm  = (const float*)d_in[4];   // [F, F]
    const float* b   = (const float*)d_in[5];   // [F]
    float* out = (float*)d_out;                 // [N, 2F]

    int n_atoms = in_sizes[0] / F;
    int n_pairs = in_sizes[2];

    int prep_n = (n_pairs > F * F) ? n_pairs : F * F;
    prep_kernel<<<(prep_n + 255) / 256, 256>>>(Wm, pl, n_pairs);

    scan_kernel<<<1, SCAN_THREADS>>>(n_atoms);

    scatter_kernel<<<(n_pairs + 255) / 256, 256>>>(pl, cut, rij, n_pairs);

    gather_kernel<<<(n_atoms + 7) / 8, 256>>>((const ulonglong2*)A, out, n_atoms);

    {
        int smem = F * F * 4 + 3 * GA * VS_STRIDE * 8;   // 64KB + 49.9KB
        cudaFuncSetAttribute(gemm_norm_kernel,
                             cudaFuncAttributeMaxDynamicSharedMemorySize, smem);
        gemm_norm_kernel<<<296, GT, smem>>>(b, out, n_atoms);
    }
}